// round 3
// baseline (speedup 1.0000x reference)
#include <cuda_runtime.h>

#define BB   4
#define SS   4096
#define DIN  1024
#define DH   64
#define MROWS (BB*SS)

__device__ float g_Q[MROWS * DH];
__device__ float g_K[MROWS * DH];
__device__ float g_V[MROWS * DH];

typedef unsigned long long u64;

// packed fp32x2 FMA: c.lo += a.lo*b.lo ; c.hi += a.hi*b.hi
__device__ __forceinline__ void fma2(u64& c, u64 a, u64 b) {
    asm("fma.rn.f32x2 %0, %1, %2, %0;" : "+l"(c) : "l"(a), "l"(b));
}
__device__ __forceinline__ float fold2(u64 v) {
    float lo, hi;
    asm("mov.b64 {%0, %1}, %2;" : "=f"(lo), "=f"(hi) : "l"(v));
    return lo + hi;
}

// ---------------------------------------------------------------------------
// Kernel 1: fused QKV projection  out = relu(X @ W + b), f32x2 packed over k.
// Tile 64 rows x 64 cols, BK=64. 256 threads (16x16), micro 4x4, 2 CTAs/SM.
// ---------------------------------------------------------------------------
__global__ __launch_bounds__(256, 2) void qkv_kernel(
    const float* __restrict__ X,
    const float* __restrict__ Wq, const float* __restrict__ bq,
    const float* __restrict__ Wk, const float* __restrict__ bk,
    const float* __restrict__ Wv, const float* __restrict__ bv)
{
    const float* W; const float* bias; float* out;
    if (blockIdx.y == 0)      { W = Wq; bias = bq; out = g_Q; }
    else if (blockIdx.y == 1) { W = Wk; bias = bk; out = g_K; }
    else                      { W = Wv; bias = bv; out = g_V; }

    __shared__ float Xs[64 * 68];     // natural [row][k], stride 68
    __shared__ float Wst[64 * 64];    // [n][k-chunks swizzled], stride 64

    const int t  = threadIdx.x;
    const int tx = t & 15;
    const int ty = t >> 4;
    const int m0 = blockIdx.x * 64;

    u64 acc[4][4] = {};

    for (int k0 = 0; k0 < DIN; k0 += 64) {
        __syncthreads();
        #pragma unroll
        for (int u = 0; u < 4; u++) {
            int cidx = t + 256 * u;
            int row  = cidx >> 4;
            int c4   = cidx & 15;
            *(float4*)&Xs[row * 68 + c4 * 4] =
                *(const float4*)&X[(m0 + row) * DIN + k0 + c4 * 4];
        }
        // W transposed: W[k][n] -> Wst[n][ ((k>>2)^(n>>2))*4 + (k&3) ]
        #pragma unroll
        for (int u = 0; u < 4; u++) {
            int cidx = t + 256 * u;
            int kr   = cidx >> 4;
            int c4   = cidx & 15;
            float4 wv = *(const float4*)&W[(k0 + kr) * DH + c4 * 4];
            int chunk = (kr >> 2) ^ c4;
            int word  = kr & 3;
            Wst[(4 * c4 + 0) * 64 + (chunk << 2) + word] = wv.x;
            Wst[(4 * c4 + 1) * 64 + (chunk << 2) + word] = wv.y;
            Wst[(4 * c4 + 2) * 64 + (chunk << 2) + word] = wv.z;
            Wst[(4 * c4 + 3) * 64 + (chunk << 2) + word] = wv.w;
        }
        __syncthreads();

        #pragma unroll 4
        for (int dc = 0; dc < 16; dc++) {
            u64 wp[4][2];
            #pragma unroll
            for (int j = 0; j < 4; j++) {
                ulonglong2 wv = *(const ulonglong2*)&Wst[(4 * tx + j) * 64 + ((dc ^ tx) << 2)];
                wp[j][0] = wv.x; wp[j][1] = wv.y;
            }
            #pragma unroll
            for (int i = 0; i < 4; i++) {
                ulonglong2 xv = *(const ulonglong2*)&Xs[(4 * ty + i) * 68 + dc * 4];
                #pragma unroll
                for (int j = 0; j < 4; j++) {
                    fma2(acc[i][j], xv.x, wp[j][0]);
                    fma2(acc[i][j], xv.y, wp[j][1]);
                }
            }
        }
    }

    float4 bi = *(const float4*)&bias[4 * tx];
    #pragma unroll
    for (int i = 0; i < 4; i++) {
        float4 r;
        r.x = fmaxf(fold2(acc[i][0]) + bi.x, 0.f);
        r.y = fmaxf(fold2(acc[i][1]) + bi.y, 0.f);
        r.z = fmaxf(fold2(acc[i][2]) + bi.z, 0.f);
        r.w = fmaxf(fold2(acc[i][3]) + bi.w, 0.f);
        *(float4*)&out[(m0 + 4 * ty + i) * DH + 4 * tx] = r;
    }
}

// ---------------------------------------------------------------------------
// Kernel 2: flash attention, f32x2 packed over reduction dims.
// Bq=64, Bk=64. 256 threads (16x16), micro 4x4. 2 CTAs/SM (16 warps/SM).
// ---------------------------------------------------------------------------
__global__ __launch_bounds__(256, 2) void attn_kernel(
    const float* __restrict__ mask, float* __restrict__ out)
{
    extern __shared__ float sm[];
    float* Qs  = sm;                 // [64][68]  natural  Qs[r][d]
    float* Ks  = Qs  + 64 * 68;      // [64][64]  K[kc][d] chunks swizzled
    float* Vst = Ks  + 64 * 64;      // [64][64]  V^T: row=dcol, chunks over kk swizzled
    float* Ps  = Vst + 64 * 64;      // [64][68]  natural  Ps[r][kk]

    const int t  = threadIdx.x;
    const int tx = t & 15;
    const int ty = t >> 4;
    const int b  = blockIdx.y;
    const int q0 = blockIdx.x * 64;
    const int base = b * SS;

    // stage Q once (natural layout)
    #pragma unroll
    for (int u = 0; u < 4; u++) {
        int cidx = t + 256 * u;          // 0..1023
        int row  = cidx >> 4;            // 0..63
        int c4   = cidx & 15;
        *(float4*)&Qs[row * 68 + c4 * 4] =
            *(const float4*)&g_Q[(base + q0 + row) * DH + c4 * 4];
    }

    float o[4][4] = {};
    float mrow[4], lrow[4] = {};
    #pragma unroll
    for (int i = 0; i < 4; i++) mrow[i] = -1e30f;

    for (int kt = 0; kt < SS / 64; kt++) {
        const int k0 = kt * 64;
        __syncthreads();   // prior readers of Ks/Vst/Ps done
        // stage K: K[kc][d] -> Ks[kc*64 + ((d>>2 ^ kc>>2)<<2) + (d&3)]
        #pragma unroll
        for (int u = 0; u < 4; u++) {
            int cidx = t + 256 * u;
            int kc   = cidx >> 4;
            int c4   = cidx & 15;
            float4 kv = *(const float4*)&g_K[(base + k0 + kc) * DH + c4 * 4];
            *(float4*)&Ks[kc * 64 + ((c4 ^ (kc >> 2)) << 2)] = kv;
        }
        // stage V transposed: V[kk][j] -> Vst[j*64 + ((kk>>2 ^ j>>2)<<2) + (kk&3)]
        #pragma unroll
        for (int u = 0; u < 4; u++) {
            int cidx = t + 256 * u;
            int kk   = cidx >> 4;
            int c4   = cidx & 15;
            float4 vv = *(const float4*)&g_V[(base + k0 + kk) * DH + c4 * 4];
            int chunk = (kk >> 2) ^ c4;
            int word  = kk & 3;
            Vst[(4 * c4 + 0) * 64 + (chunk << 2) + word] = vv.x;
            Vst[(4 * c4 + 1) * 64 + (chunk << 2) + word] = vv.y;
            Vst[(4 * c4 + 2) * 64 + (chunk << 2) + word] = vv.z;
            Vst[(4 * c4 + 3) * 64 + (chunk << 2) + word] = vv.w;
        }
        __syncthreads();

        // ---- S = Q @ K^T, packed over d ----
        u64 acc[4][4] = {};
        #pragma unroll 4
        for (int dc = 0; dc < 16; dc++) {
            u64 kp[4][2];
            #pragma unroll
            for (int j = 0; j < 4; j++) {
                ulonglong2 kv = *(const ulonglong2*)&Ks[(4 * tx + j) * 64 + ((dc ^ tx) << 2)];
                kp[j][0] = kv.x; kp[j][1] = kv.y;
            }
            #pragma unroll
            for (int i = 0; i < 4; i++) {
                ulonglong2 qv = *(const ulonglong2*)&Qs[(4 * ty + i) * 68 + dc * 4];
                #pragma unroll
                for (int j = 0; j < 4; j++) {
                    fma2(acc[i][j], qv.x, kp[j][0]);
                    fma2(acc[i][j], qv.y, kp[j][1]);
                }
            }
        }

        // ---- online softmax, write P ----
        float scl[4];
        #pragma unroll
        for (int i = 0; i < 4; i++) {
            float s0 = fold2(acc[i][0]);
            float s1 = fold2(acc[i][1]);
            float s2 = fold2(acc[i][2]);
            float s3 = fold2(acc[i][3]);
            float mi = fmaxf(fmaxf(s0, s1), fmaxf(s2, s3));
            #pragma unroll
            for (int off = 8; off >= 1; off >>= 1)
                mi = fmaxf(mi, __shfl_xor_sync(0xffffffffu, mi, off));
            float mnew = fmaxf(mrow[i], mi);
            scl[i] = __expf(mrow[i] - mnew);
            mrow[i] = mnew;
            float e0 = __expf(s0 - mnew);
            float e1 = __expf(s1 - mnew);
            float e2 = __expf(s2 - mnew);
            float e3 = __expf(s3 - mnew);
            float li = e0 + e1 + e2 + e3;
            #pragma unroll
            for (int off = 8; off >= 1; off >>= 1)
                li += __shfl_xor_sync(0xffffffffu, li, off);
            lrow[i] = lrow[i] * scl[i] + li;
            *(float4*)&Ps[(4 * ty + i) * 68 + 4 * tx] = make_float4(e0, e1, e2, e3);
        }
        __syncthreads();

        // ---- O = O*scl + P @ V, packed over kk ----
        #pragma unroll
        for (int i = 0; i < 4; i++)
            #pragma unroll
            for (int j = 0; j < 4; j++) acc[i][j] = 0ull;

        #pragma unroll 4
        for (int kc = 0; kc < 16; kc++) {
            u64 vp[4][2];
            #pragma unroll
            for (int j = 0; j < 4; j++) {
                ulonglong2 vv = *(const ulonglong2*)&Vst[(4 * tx + j) * 64 + ((kc ^ tx) << 2)];
                vp[j][0] = vv.x; vp[j][1] = vv.y;
            }
            #pragma unroll
            for (int i = 0; i < 4; i++) {
                ulonglong2 pv = *(const ulonglong2*)&Ps[(4 * ty + i) * 68 + kc * 4];
                #pragma unroll
                for (int j = 0; j < 4; j++) {
                    fma2(acc[i][j], pv.x, vp[j][0]);
                    fma2(acc[i][j], pv.y, vp[j][1]);
                }
            }
        }
        #pragma unroll
        for (int i = 0; i < 4; i++)
            #pragma unroll
            for (int j = 0; j < 4; j++)
                o[i][j] = o[i][j] * scl[i] + fold2(acc[i][j]);
    }

    // epilogue: normalize, apply mask
    #pragma unroll
    for (int i = 0; i < 4; i++) {
        int q = q0 + 4 * ty + i;
        float mv  = mask[base + q];
        float inv = mv / lrow[i];
        float4 r = make_float4(o[i][0] * inv, o[i][1] * inv,
                               o[i][2] * inv, o[i][3] * inv);
        *(float4*)&out[(size_t)(base + q) * DH + 4 * tx] = r;
    }
}

// ---------------------------------------------------------------------------
extern "C" void kernel_launch(void* const* d_in, const int* in_sizes, int n_in,
                              void* d_out, int out_size)
{
    const float* X    = (const float*)d_in[0];
    const float* mask = (const float*)d_in[1];
    const float* Wq   = (const float*)d_in[2];
    const float* bq   = (const float*)d_in[3];
    const float* Wk   = (const float*)d_in[4];
    const float* bk   = (const float*)d_in[5];
    const float* Wv   = (const float*)d_in[6];
    const float* bv   = (const float*)d_in[7];

    const int smem_attn = (64 * 68 + 64 * 64 + 64 * 64 + 64 * 68) * sizeof(float); // 67584
    cudaFuncSetAttribute(attn_kernel,
                         cudaFuncAttributeMaxDynamicSharedMemorySize, smem_attn);

    qkv_kernel<<<dim3(MROWS / 64, 3), 256>>>(X, Wq, bq, Wk, bk, Wv, bv);
    attn_kernel<<<dim3(SS / 64, BB), 256, smem_attn>>>(mask, (float*)d_out);
}

// round 4
// speedup vs baseline: 2.5212x; 2.5212x over previous
#include <cuda_runtime.h>

typedef unsigned int u32;
typedef unsigned short u16;

#define BB 4
#define SS 4096
#define DIN 1024
#define DH 64
#define MROWS (BB*SS)
#define NSPLIT 2
#define KTS (SS/64)
#define KT_PER (KTS/NSPLIT)

// ---------------- scratch (static device memory; no allocations) ----------
__device__ u16 g_Xh[MROWS*DIN], g_Xl[MROWS*DIN];           // X split bf16
__device__ u16 g_Wth[3][DH*DIN], g_Wtl[3][DH*DIN];         // W^T split bf16 [out][din]
__device__ u16 g_Qh[MROWS*DH], g_Ql[MROWS*DH];             // [row][d]
__device__ u16 g_Kh[MROWS*DH], g_Kl[MROWS*DH];             // [row][d]
__device__ u16 g_Vh[MROWS*DH], g_Vl[MROWS*DH];             // transposed [b][d][s]
__device__ float g_Op[NSPLIT][MROWS*DH];                   // unnormalized partial O
__device__ float g_m[NSPLIT][MROWS];
__device__ float g_l[NSPLIT][MROWS];

// ---------------- helpers --------------------------------------------------
__device__ __forceinline__ u32 packbf(float lo, float hi){
    u32 r; asm("cvt.rn.bf16x2.f32 %0, %1, %2;" : "=r"(r) : "f"(hi), "f"(lo)); return r;
}
__device__ __forceinline__ float bflo(u32 p){ return __uint_as_float(p << 16); }
__device__ __forceinline__ float bfhi(u32 p){ return __uint_as_float(p & 0xffff0000u); }
__device__ __forceinline__ u32 smaddr(const void* p){ return (u32)__cvta_generic_to_shared(p); }

__device__ __forceinline__ void ldsm4(u32& r0,u32& r1,u32& r2,u32& r3, u32 a){
    asm volatile("ldmatrix.sync.aligned.m8n8.x4.shared.b16 {%0,%1,%2,%3}, [%4];"
        : "=r"(r0),"=r"(r1),"=r"(r2),"=r"(r3) : "r"(a));
}
__device__ __forceinline__ void mma_bf(float* c, const u32* a, u32 b0, u32 b1){
    asm volatile("mma.sync.aligned.m16n8k16.row.col.f32.bf16.bf16.f32 "
        "{%0,%1,%2,%3},{%4,%5,%6,%7},{%8,%9},{%0,%1,%2,%3};"
        : "+f"(c[0]),"+f"(c[1]),"+f"(c[2]),"+f"(c[3])
        : "r"(a[0]),"r"(a[1]),"r"(a[2]),"r"(a[3]),"r"(b0),"r"(b1));
}

// ---------------- kernel: convert X to split bf16 --------------------------
__global__ __launch_bounds__(256) void cvt_x(const float* __restrict__ X){
    size_t i = (size_t)(blockIdx.x*256 + threadIdx.x) * 4;
    float4 v = *(const float4*)&X[i];
    u32 h01 = packbf(v.x, v.y), h23 = packbf(v.z, v.w);
    u32 l01 = packbf(v.x - bflo(h01), v.y - bfhi(h01));
    u32 l23 = packbf(v.z - bflo(h23), v.w - bfhi(h23));
    *(uint2*)&g_Xh[i] = make_uint2(h01, h23);
    *(uint2*)&g_Xl[i] = make_uint2(l01, l23);
}

// ---------------- kernel: convert+transpose weights ------------------------
__global__ __launch_bounds__(256) void cvt_w(const float* __restrict__ Wq,
                                             const float* __restrict__ Wk,
                                             const float* __restrict__ Wv){
    int id = blockIdx.x*256 + threadIdx.x;     // 3 * 64 * 1024
    int w = id >> 16; int r = id & 65535;
    int n = r >> 10, k = r & 1023;
    const float* W = (w==0) ? Wq : (w==1) ? Wk : Wv;
    float x = W[k*DH + n];
    u32 p = packbf(x, 0.f);
    u32 q = packbf(x - bflo(p), 0.f);
    g_Wth[w][n*DIN + k] = (u16)(p & 0xffff);
    g_Wtl[w][n*DIN + k] = (u16)(q & 0xffff);
}

__device__ __forceinline__ void storeV(int r, int c, float v){
    int bb = r >> 12, s = r & 4095;
    u32 p = packbf(v, 0.f);
    g_Vh[(size_t)(bb*64 + c)*SS + s] = (u16)(p & 0xffff);
    u32 q = packbf(v - bflo(p), 0.f);
    g_Vl[(size_t)(bb*64 + c)*SS + s] = (u16)(q & 0xffff);
}

// ---------------- kernel: QKV projection via MMA ---------------------------
// grid (MROWS/64, 3), 128 threads (4 warps x 16 rows). out = relu(X@W + b),
// 3-product split-bf16, fp32 accumulate, epilogue splits to bf16 hi/lo.
__global__ __launch_bounds__(128, 4) void qkv_mma(
    const float* __restrict__ bq, const float* __restrict__ bk,
    const float* __restrict__ bv)
{
    __shared__ u16 Xs_h[64*72], Xs_l[64*72], Ws_h[64*72], Ws_l[64*72];
    const int t = threadIdx.x, lane = t & 31, warp = t >> 5;
    const int w = blockIdx.y;
    const int m0 = blockIdx.x * 64;
    const u16* Wth = g_Wth[w]; const u16* Wtl = g_Wtl[w];
    const float* bias = (w==0) ? bq : (w==1) ? bk : bv;

    const u32 aoff = ((16*warp + (lane&15))*72 + ((lane>>4)<<3)) * 2;
    const u32 boff = (((lane&7) + ((lane>>4)<<3))*72 + (((lane>>3)&1)<<3)) * 2;
    const u32 a_h = smaddr(Xs_h) + aoff, a_l = smaddr(Xs_l) + aoff;
    const u32 b_h = smaddr(Ws_h) + boff, b_l = smaddr(Ws_l) + boff;

    float acc[8][4] = {};
    for (int c16 = 0; c16 < 16; c16++){
        __syncthreads();
        #pragma unroll
        for (int u = 0; u < 4; u++){
            int idx = t + 128*u; int row = idx >> 3, q4 = idx & 7;
            *(uint4*)&Xs_h[row*72 + q4*8] = *(const uint4*)&g_Xh[(size_t)(m0+row)*DIN + c16*64 + q4*8];
            *(uint4*)&Xs_l[row*72 + q4*8] = *(const uint4*)&g_Xl[(size_t)(m0+row)*DIN + c16*64 + q4*8];
            *(uint4*)&Ws_h[row*72 + q4*8] = *(const uint4*)&Wth[(size_t)row*DIN + c16*64 + q4*8];
            *(uint4*)&Ws_l[row*72 + q4*8] = *(const uint4*)&Wtl[(size_t)row*DIN + c16*64 + q4*8];
        }
        __syncthreads();
        #pragma unroll
        for (int ks = 0; ks < 4; ks++){
            u32 ah[4], al[4];
            ldsm4(ah[0],ah[1],ah[2],ah[3], a_h + ks*32);
            ldsm4(al[0],al[1],al[2],al[3], a_l + ks*32);
            #pragma unroll
            for (int p = 0; p < 4; p++){
                u32 bh[4], bl[4];
                ldsm4(bh[0],bh[1],bh[2],bh[3], b_h + p*2304 + ks*32);
                ldsm4(bl[0],bl[1],bl[2],bl[3], b_l + p*2304 + ks*32);
                mma_bf(acc[2*p],   ah, bh[0], bh[1]);
                mma_bf(acc[2*p],   ah, bl[0], bl[1]);
                mma_bf(acc[2*p],   al, bh[0], bh[1]);
                mma_bf(acc[2*p+1], ah, bh[2], bh[3]);
                mma_bf(acc[2*p+1], ah, bl[2], bl[3]);
                mma_bf(acc[2*p+1], al, bh[2], bh[3]);
            }
        }
    }

    const int g = lane >> 2, t2 = lane & 3;
    const int r0 = m0 + 16*warp + g, r1 = r0 + 8;
    #pragma unroll
    for (int nb = 0; nb < 8; nb++){
        int col = nb*8 + t2*2;
        float b0v = bias[col], b1v = bias[col+1];
        float v00 = fmaxf(acc[nb][0] + b0v, 0.f);
        float v01 = fmaxf(acc[nb][1] + b1v, 0.f);
        float v10 = fmaxf(acc[nb][2] + b0v, 0.f);
        float v11 = fmaxf(acc[nb][3] + b1v, 0.f);
        if (w == 2){
            storeV(r0, col, v00); storeV(r0, col+1, v01);
            storeV(r1, col, v10); storeV(r1, col+1, v11);
        } else {
            u16* Oh = (w==0) ? g_Qh : g_Kh;
            u16* Ol = (w==0) ? g_Ql : g_Kl;
            u32 h = packbf(v00, v01);
            u32 lo = packbf(v00 - bflo(h), v01 - bfhi(h));
            *(u32*)&Oh[(size_t)r0*DH + col] = h; *(u32*)&Ol[(size_t)r0*DH + col] = lo;
            h = packbf(v10, v11);
            lo = packbf(v10 - bflo(h), v11 - bfhi(h));
            *(u32*)&Oh[(size_t)r1*DH + col] = h; *(u32*)&Ol[(size_t)r1*DH + col] = lo;
        }
    }
}

// ---------------- kernel: flash attention via MMA, KV-split ----------------
// grid (SS/64, BB, NSPLIT), 128 threads. Bq=64, Bk=64.
__global__ __launch_bounds__(128, 4) void attn_mma()
{
    extern __shared__ u16 smu[];
    u16* Qh = smu;
    u16* Ql = Qh + 4608;
    u16* Kh = Ql + 4608;
    u16* Kl = Kh + 4608;
    u16* Vh = Kl + 4608;
    u16* Vl = Vh + 4608;

    const int t = threadIdx.x, lane = t & 31, warp = t >> 5;
    const int b = blockIdx.y, z = blockIdx.z;
    const int q0 = blockIdx.x * 64;
    const int base = b * SS;

    #pragma unroll
    for (int u = 0; u < 4; u++){
        int idx = t + 128*u; int row = idx >> 3, q4 = idx & 7;
        *(uint4*)&Qh[row*72 + q4*8] = *(const uint4*)&g_Qh[(size_t)(base+q0+row)*DH + q4*8];
        *(uint4*)&Ql[row*72 + q4*8] = *(const uint4*)&g_Ql[(size_t)(base+q0+row)*DH + q4*8];
    }
    __syncthreads();

    const u32 aoff = ((16*warp + (lane&15))*72 + ((lane>>4)<<3)) * 2;
    const u32 boff = (((lane&7) + ((lane>>4)<<3))*72 + (((lane>>3)&1)<<3)) * 2;
    const u32 qh_a = smaddr(Qh) + aoff, ql_a = smaddr(Ql) + aoff;
    const u32 kh_b = smaddr(Kh) + boff, kl_b = smaddr(Kl) + boff;
    const u32 vh_b = smaddr(Vh) + boff, vl_b = smaddr(Vl) + boff;

    u32 qhf[4][4];
    #pragma unroll
    for (int ks = 0; ks < 4; ks++)
        ldsm4(qhf[ks][0],qhf[ks][1],qhf[ks][2],qhf[ks][3], qh_a + ks*32);

    float o[8][4] = {};
    float mr[2] = {-3e38f, -3e38f};
    float lr[2] = {0.f, 0.f};

    for (int it = 0; it < KT_PER; it++){
        const int k0 = (z*KT_PER + it) * 64;
        __syncthreads();
        #pragma unroll
        for (int u = 0; u < 4; u++){
            int idx = t + 128*u; int row = idx >> 3, q4 = idx & 7;
            *(uint4*)&Kh[row*72 + q4*8] = *(const uint4*)&g_Kh[(size_t)(base+k0+row)*DH + q4*8];
            *(uint4*)&Kl[row*72 + q4*8] = *(const uint4*)&g_Kl[(size_t)(base+k0+row)*DH + q4*8];
            *(uint4*)&Vh[row*72 + q4*8] = *(const uint4*)&g_Vh[(size_t)(b*64+row)*SS + k0 + q4*8];
            *(uint4*)&Vl[row*72 + q4*8] = *(const uint4*)&g_Vl[(size_t)(b*64+row)*SS + k0 + q4*8];
        }
        __syncthreads();

        // ---- S = Q @ K^T (split: qh*kh + qh*kl + ql*kh) ----
        float s[8][4] = {};
        #pragma unroll
        for (int ks = 0; ks < 4; ks++){
            u32 qlf[4];
            ldsm4(qlf[0],qlf[1],qlf[2],qlf[3], ql_a + ks*32);
            #pragma unroll
            for (int p = 0; p < 4; p++){
                u32 bh[4], bl[4];
                ldsm4(bh[0],bh[1],bh[2],bh[3], kh_b + p*2304 + ks*32);
                ldsm4(bl[0],bl[1],bl[2],bl[3], kl_b + p*2304 + ks*32);
                mma_bf(s[2*p],   qhf[ks], bh[0], bh[1]);
                mma_bf(s[2*p],   qhf[ks], bl[0], bl[1]);
                mma_bf(s[2*p],   qlf,     bh[0], bh[1]);
                mma_bf(s[2*p+1], qhf[ks], bh[2], bh[3]);
                mma_bf(s[2*p+1], qhf[ks], bl[2], bl[3]);
                mma_bf(s[2*p+1], qlf,     bh[2], bh[3]);
            }
        }

        // ---- online softmax (rows g, g+8), quad-lane reductions ----
        #pragma unroll
        for (int ri = 0; ri < 2; ri++){
            float mi = -3e38f;
            #pragma unroll
            for (int nb = 0; nb < 8; nb++)
                mi = fmaxf(mi, fmaxf(s[nb][2*ri], s[nb][2*ri+1]));
            mi = fmaxf(mi, __shfl_xor_sync(0xffffffffu, mi, 1));
            mi = fmaxf(mi, __shfl_xor_sync(0xffffffffu, mi, 2));
            float mnew = fmaxf(mr[ri], mi);
            float scl = __expf(mr[ri] - mnew);
            mr[ri] = mnew;
            float li = 0.f;
            #pragma unroll
            for (int nb = 0; nb < 8; nb++){
                float e0 = __expf(s[nb][2*ri]   - mnew);
                float e1 = __expf(s[nb][2*ri+1] - mnew);
                s[nb][2*ri] = e0; s[nb][2*ri+1] = e1;
                li += e0 + e1;
                o[nb][2*ri]   *= scl;
                o[nb][2*ri+1] *= scl;
            }
            li += __shfl_xor_sync(0xffffffffu, li, 1);
            li += __shfl_xor_sync(0xffffffffu, li, 2);
            lr[ri] = lr[ri]*scl + li;
        }

        // ---- P C-frag -> A-frag in registers (no shuffles), split ----
        u32 ph[4][4], pl[4][4];
        #pragma unroll
        for (int ks = 0; ks < 4; ks++){
            ph[ks][0] = packbf(s[2*ks][0],   s[2*ks][1]);
            ph[ks][1] = packbf(s[2*ks][2],   s[2*ks][3]);
            ph[ks][2] = packbf(s[2*ks+1][0], s[2*ks+1][1]);
            ph[ks][3] = packbf(s[2*ks+1][2], s[2*ks+1][3]);
            pl[ks][0] = packbf(s[2*ks][0]   - bflo(ph[ks][0]), s[2*ks][1]   - bfhi(ph[ks][0]));
            pl[ks][1] = packbf(s[2*ks][2]   - bflo(ph[ks][1]), s[2*ks][3]   - bfhi(ph[ks][1]));
            pl[ks][2] = packbf(s[2*ks+1][0] - bflo(ph[ks][2]), s[2*ks+1][1] - bfhi(ph[ks][2]));
            pl[ks][3] = packbf(s[2*ks+1][2] - bflo(ph[ks][3]), s[2*ks+1][3] - bfhi(ph[ks][3]));
        }

        // ---- O += P @ V (split) ----
        #pragma unroll
        for (int ks = 0; ks < 4; ks++){
            #pragma unroll
            for (int p = 0; p < 4; p++){
                u32 vh4[4], vl4[4];
                ldsm4(vh4[0],vh4[1],vh4[2],vh4[3], vh_b + p*2304 + ks*32);
                ldsm4(vl4[0],vl4[1],vl4[2],vl4[3], vl_b + p*2304 + ks*32);
                mma_bf(o[2*p],   ph[ks], vh4[0], vh4[1]);
                mma_bf(o[2*p],   ph[ks], vl4[0], vl4[1]);
                mma_bf(o[2*p],   pl[ks], vh4[0], vh4[1]);
                mma_bf(o[2*p+1], ph[ks], vh4[2], vh4[3]);
                mma_bf(o[2*p+1], ph[ks], vl4[2], vl4[3]);
                mma_bf(o[2*p+1], pl[ks], vh4[2], vh4[3]);
            }
        }
    }

    // write unnormalized partials + stats
    const int g = lane >> 2, t2 = lane & 3;
    const int r0 = base + q0 + 16*warp + g, r1 = r0 + 8;
    #pragma unroll
    for (int nb = 0; nb < 8; nb++){
        *(float2*)&g_Op[z][(size_t)r0*DH + nb*8 + t2*2] = make_float2(o[nb][0], o[nb][1]);
        *(float2*)&g_Op[z][(size_t)r1*DH + nb*8 + t2*2] = make_float2(o[nb][2], o[nb][3]);
    }
    if (t2 == 0){
        g_m[z][r0] = mr[0]; g_l[z][r0] = lr[0];
        g_m[z][r1] = mr[1]; g_l[z][r1] = lr[1];
    }
}

// ---------------- kernel: flash split combine + mask -----------------------
__global__ __launch_bounds__(256) void combine(const float* __restrict__ mask,
                                               float* __restrict__ out){
    int idx = blockIdx.x*256 + threadIdx.x;   // row*16 + dquad
    int row = idx >> 4, dq = idx & 15;
    float m0 = g_m[0][row], m1 = g_m[1][row];
    float l0 = g_l[0][row], l1 = g_l[1][row];
    float mm = fmaxf(m0, m1);
    float w0 = __expf(m0 - mm), w1 = __expf(m1 - mm);
    float f = mask[row] / (w0*l0 + w1*l1);
    float4 a = *(const float4*)&g_Op[0][(size_t)row*DH + dq*4];
    float4 c = *(const float4*)&g_Op[1][(size_t)row*DH + dq*4];
    float4 r;
    r.x = (a.x*w0 + c.x*w1) * f;
    r.y = (a.y*w0 + c.y*w1) * f;
    r.z = (a.z*w0 + c.z*w1) * f;
    r.w = (a.w*w0 + c.w*w1) * f;
    *(float4*)&out[(size_t)row*DH + dq*4] = r;
}

// ---------------------------------------------------------------------------
extern "C" void kernel_launch(void* const* d_in, const int* in_sizes, int n_in,
                              void* d_out, int out_size)
{
    const float* X    = (const float*)d_in[0];
    const float* mask = (const float*)d_in[1];
    const float* Wq   = (const float*)d_in[2];
    const float* bq   = (const float*)d_in[3];
    const float* Wk   = (const float*)d_in[4];
    const float* bk   = (const float*)d_in[5];
    const float* Wv   = (const float*)d_in[6];
    const float* bv   = (const float*)d_in[7];

    const int smem_attn = 6 * 64 * 72 * (int)sizeof(u16);  // 55296 B
    cudaFuncSetAttribute(attn_mma,
                         cudaFuncAttributeMaxDynamicSharedMemorySize, smem_attn);

    cvt_x<<<MROWS*DIN/4/256, 256>>>(X);
    cvt_w<<<3*DH*DIN/256, 256>>>(Wq, Wk, Wv);
    qkv_mma<<<dim3(MROWS/64, 3), 128>>>(bq, bk, bv);
    attn_mma<<<dim3(SS/64, BB, NSPLIT), 128, smem_attn>>>();
    combine<<<MROWS*DH/4/256, 256>>>(mask, (float*)d_out);
}